// round 4
// baseline (speedup 1.0000x reference)
#include <cuda_runtime.h>
#include <cstdint>

#define IMG_W 512
#define IMG_H 512
#define PLANES 64
#define PLANE_STRIDE (IMG_H * IMG_W)
#define NPIX (PLANES * PLANE_STRIDE)

#define BAND 64
#define CHUNK 8
#define NCHUNK (BAND / CHUNK)              // 8 chunks per band
#define BANDS_PER_PLANE (IMG_H / BAND)     // 8
#define NBLOCKS (PLANES * BANDS_PER_PLANE) // 512
#define EPS 1e-10f

#define ROW_BYTES (IMG_W * 4)              // 2048
#define STAGE_IMG_BYTES (CHUNK * ROW_BYTES)        // 16384
#define STAGE_BYTES (2 * STAGE_IMG_BYTES)          // 32768 (both images)
#define OFF_PRE  (3 * STAGE_BYTES)                 // 98304  : halo row R0-1, [img][512]
#define OFF_POST (OFF_PRE + 2 * ROW_BYTES)         // 102400 : halo row R0+BAND
#define OFF_MBAR (OFF_POST + 2 * ROW_BYTES)        // 106496 : mbar[0..2]=stages, [3]=halo
#define SMEM_TOTAL (OFF_MBAR + 64)                 // 106560

// persistent scratch (statically zero-init; last block resets each call)
__device__ double g_acc;
__device__ unsigned int g_count;

__device__ __forceinline__ uint32_t smem_u32(const void* p) {
    uint32_t a;
    asm("{ .reg .u64 t; cvta.to.shared.u64 t, %1; cvt.u32.u64 %0, t; }" : "=r"(a) : "l"(p));
    return a;
}
__device__ __forceinline__ void mbar_init(uint32_t mbar, uint32_t count) {
    asm volatile("mbarrier.init.shared.b64 [%0], %1;" :: "r"(mbar), "r"(count) : "memory");
}
__device__ __forceinline__ void mbar_expect_tx(uint32_t mbar, uint32_t bytes) {
    asm volatile("mbarrier.arrive.expect_tx.shared.b64 _, [%0], %1;" :: "r"(mbar), "r"(bytes) : "memory");
}
__device__ __forceinline__ void mbar_wait(uint32_t mbar, uint32_t parity) {
    asm volatile(
        "{\n\t.reg .pred P;\n\t"
        "WAIT_%=:\n\t"
        "mbarrier.try_wait.parity.acquire.cta.shared::cta.b64 P, [%0], %1, 0x989680;\n\t"
        "@P bra.uni DONE_%=;\n\t"
        "bra.uni WAIT_%=;\n\t"
        "DONE_%=:\n\t}"
        :: "r"(mbar), "r"(parity) : "memory");
}
__device__ __forceinline__ void bulk_g2s(uint32_t dst, const void* src, uint32_t bytes, uint32_t mbar) {
    asm volatile(
        "cp.async.bulk.shared::cta.global.mbarrier::complete_tx::bytes [%0], [%1], %2, [%3];"
        :: "r"(dst), "l"(src), "r"(bytes), "r"(mbar) : "memory");
}

// smem row pointer for global row g (R0-1 .. R0+BAND), image img
__device__ __forceinline__ const float* rowp(const char* sm, int R0, int g, int img) {
    if (g < R0)          return (const float*)(sm + OFF_PRE  + img * ROW_BYTES);
    if (g >= R0 + BAND)  return (const float*)(sm + OFF_POST + img * ROW_BYTES);
    const int d  = g - R0;
    const int st = (d >> 3) % 3;
    return (const float*)(sm + ((st * 2 + img) * CHUNK + (d & 7)) * ROW_BYTES);
}

__global__ __launch_bounds__(256) void ngf_kernel(
    const float* __restrict__ I0, const float* __restrict__ I1,
    float* __restrict__ out)
{
    extern __shared__ char sm[];
    const int t    = threadIdx.x;
    const int lane = t & 31;
    const int cg   = t & 127;          // float4 column group 0..127
    const int h    = t >> 7;           // row-half 0/1 within each chunk
    const int plane = blockIdx.x >> 3;
    const int band  = blockIdx.x & 7;
    const int R0    = band * BAND;

    const float* __restrict__ base0 = I0 + plane * PLANE_STRIDE;
    const float* __restrict__ base1 = I1 + plane * PLANE_STRIDE;

    const uint32_t sbase = smem_u32(sm);
    const uint32_t mb0 = sbase + OFF_MBAR;           // stage barriers mb0+8*s
    const uint32_t mbh = sbase + OFF_MBAR + 24;      // halo barrier

    if (t == 0) {
        mbar_init(mb0 + 0, 1);
        mbar_init(mb0 + 8, 1);
        mbar_init(mb0 + 16, 1);
        mbar_init(mbh, 1);
    }
    __syncthreads();

    if (t == 0) {
        // halo rows (clamped at image edges)
        const int gpre  = (R0 > 0) ? R0 - 1 : 0;
        const int gpost = (R0 + BAND < IMG_H) ? R0 + BAND : IMG_H - 1;
        mbar_expect_tx(mbh, 4 * ROW_BYTES);
        bulk_g2s(sbase + OFF_PRE,             base0 + gpre  * IMG_W, ROW_BYTES, mbh);
        bulk_g2s(sbase + OFF_PRE + ROW_BYTES, base1 + gpre  * IMG_W, ROW_BYTES, mbh);
        bulk_g2s(sbase + OFF_POST,             base0 + gpost * IMG_W, ROW_BYTES, mbh);
        bulk_g2s(sbase + OFF_POST + ROW_BYTES, base1 + gpost * IMG_W, ROW_BYTES, mbh);
        // prologue: chunks 0..2
#pragma unroll
        for (int k = 0; k < 3; k++) {
            const uint32_t mb = mb0 + 8 * k;
            mbar_expect_tx(mb, STAGE_BYTES);
            bulk_g2s(sbase + (k * 2 + 0) * STAGE_IMG_BYTES, base0 + (R0 + k * CHUNK) * IMG_W, STAGE_IMG_BYTES, mb);
            bulk_g2s(sbase + (k * 2 + 1) * STAGE_IMG_BYTES, base1 + (R0 + k * CHUNK) * IMG_W, STAGE_IMG_BYTES, mb);
        }
    }

    mbar_wait(mbh, 0);
    mbar_wait(mb0, 0);       // chunk 0

    float s = 0.f;

    for (int c = 0; c < NCHUNK; c++) {
        if (c + 1 < NCHUNK)
            mbar_wait(mb0 + 8 * ((c + 1) % 3), ((c + 1) / 3) & 1);

        // ---- compute chunk c: this half handles rows [rstart, rstart+4) ----
        const int rstart = R0 + c * CHUNK + h * 4;

        const float* pc0 = rowp(sm, R0, rstart, 0);
        const float* pc1 = rowp(sm, R0, rstart, 1);
        float4 up0  = ((const float4*)rowp(sm, R0, rstart - 1, 0))[cg];
        float4 up1  = ((const float4*)rowp(sm, R0, rstart - 1, 1))[cg];
        float4 cen0 = ((const float4*)pc0)[cg];
        float4 cen1 = ((const float4*)pc1)[cg];

#pragma unroll
        for (int j = 0; j < 4; j++) {
            const float* pd0 = rowp(sm, R0, rstart + 1 + j, 0);
            const float* pd1 = rowp(sm, R0, rstart + 1 + j, 1);
            const float4 dn0 = ((const float4*)pd0)[cg];
            const float4 dn1 = ((const float4*)pd1)[cg];

            // horizontal halo: shfl within warp; warp-edge lanes read from smem
            float hl0 = __shfl_up_sync(0xFFFFFFFFu, cen0.w, 1);
            float hr0 = __shfl_down_sync(0xFFFFFFFFu, cen0.x, 1);
            float hl1 = __shfl_up_sync(0xFFFFFFFFu, cen1.w, 1);
            float hr1 = __shfl_down_sync(0xFFFFFFFFu, cen1.x, 1);
            if (lane == 0) {
                hl0 = (cg > 0) ? pc0[cg * 4 - 1] : cen0.x;
                hl1 = (cg > 0) ? pc1[cg * 4 - 1] : cen1.x;
            }
            if (lane == 31) {
                hr0 = (cg < 127) ? pc0[cg * 4 + 4] : cen0.w;
                hr1 = (cg < 127) ? pc1[cg * 4 + 4] : cen1.w;
            }

            // gx = x[min(r+1)] - x[max(r-1)]  (fwd/central/bwd diff)
            const float g0x[4] = { dn0.x - up0.x, dn0.y - up0.y, dn0.z - up0.z, dn0.w - up0.w };
            const float g1x[4] = { dn1.x - up1.x, dn1.y - up1.y, dn1.z - up1.z, dn1.w - up1.w };
            // gy = x[min(c+1)] - x[max(c-1)]
            const float g0y[4] = { cen0.y - hl0, cen0.z - cen0.x, cen0.w - cen0.y, hr0 - cen0.z };
            const float g1y[4] = { cen1.y - hl1, cen1.z - cen1.x, cen1.w - cen1.y, hr1 - cen1.z };

#pragma unroll
            for (int i = 0; i < 4; i++) {
                const float n0  = fmaf(g0x[i], g0x[i], fmaf(g0y[i], g0y[i], EPS));
                const float n1  = fmaf(g1x[i], g1x[i], fmaf(g1y[i], g1y[i], EPS));
                const float dot = fmaf(g0x[i], g1x[i], g0y[i] * g1y[i]);
                s += __fdividef(dot * dot, n0 * n1);   // == (g0/|g0| . g1/|g1|)^2
            }

            up0 = cen0; cen0 = dn0; pc0 = pd0;
            up1 = cen1; cen1 = dn1; pc1 = pd1;
        }

        __syncthreads();   // all readers of stage (c-1)%3 done

        // stage (c+2)%3 == (c-1)%3 is now free: load chunk c+2
        if (t == 0 && c >= 1 && c + 2 < NCHUNK) {
            const int k = c + 2;
            const uint32_t mb = mb0 + 8 * (k % 3);
            const uint32_t sdst = sbase + ((k % 3) * 2) * STAGE_IMG_BYTES;
            mbar_expect_tx(mb, STAGE_BYTES);
            bulk_g2s(sdst,                   base0 + (R0 + k * CHUNK) * IMG_W, STAGE_IMG_BYTES, mb);
            bulk_g2s(sdst + STAGE_IMG_BYTES, base1 + (R0 + k * CHUNK) * IMG_W, STAGE_IMG_BYTES, mb);
        }
    }

    // ---- reduction: 8 warps ----
#pragma unroll
    for (int off = 16; off > 0; off >>= 1)
        s += __shfl_xor_sync(0xFFFFFFFFu, s, off);

    __shared__ float warp_part[8];
    const int wid = t >> 5;
    if (lane == 0) warp_part[wid] = s;
    __syncthreads();

    if (t == 0) {
        double bs = 0.0;
#pragma unroll
        for (int w = 0; w < 8; w++) bs += (double)warp_part[w];
        atomicAdd(&g_acc, bs);
        __threadfence();
        const unsigned prev = atomicAdd(&g_count, 1u);
        if (prev == NBLOCKS - 1) {
            const double total = atomicAdd(&g_acc, 0.0);
            out[0] = (float)(1.0 - total / (double)NPIX);
            g_acc = 0.0;          // reset for next graph replay
            g_count = 0u;
            __threadfence();
        }
    }
}

extern "C" void kernel_launch(void* const* d_in, const int* in_sizes, int n_in,
                              void* d_out, int out_size)
{
    const float* I0 = (const float*)d_in[0];
    const float* I1 = (const float*)d_in[1];
    float* out = (float*)d_out;

    cudaFuncSetAttribute(ngf_kernel, cudaFuncAttributeMaxDynamicSharedMemorySize, SMEM_TOTAL);
    ngf_kernel<<<NBLOCKS, 256, SMEM_TOTAL>>>(I0, I1, out);
}